// round 11
// baseline (speedup 1.0000x reference)
#include <cuda_runtime.h>

// NeRF volume rendering compositing — round 11: speculation + default cache.
// (R7 tested speculation confounded with __ldcs; R8 showed __ldcs cost
//  ~3.4us wall. This round = speculation with L2-friendly default loads.)
// Inputs (metadata order):
//   d_in[0]: sigma  [B, S]    float32   (B=65536, S=512)
//   d_in[1]: dists  [B, S]    float32
//   d_in[2]: rgb    [B, S, 3] float32
//   d_in[3]: bg_col [3]       float32
// Output: rgb_map [B, 3] float32
//
//   x = sigma*dists*25; alpha = 1-exp(-x); T = excl cumprod(exp(-x)+1e-10)
//   w = alpha*T; out_c = sum w*clip(rgb,0,1) + (1-sum w)*bg_c
//
// Two rays per warp (16-lane segments), 64 samples/round, 4/lane, float4,
// default-cached loads (65 MB working set stays L2-resident across graph
// replays). Round 0 peeled: lanes 0..SPEC-1 load rgb UNCONDITIONALLY,
// batched with sigma/dists (addresses scan-independent) -> ONE L2 latency
// exposure per warp instead of two. Spec lanes accumulate with exact
// weights regardless of T (strictly more accurate than predicated skip;
// R7 measured rel_err 1.35e-5). Lanes >= SPEC and rounds 1..7 keep the
// scan-predicated path (~0.9% of rays at tau=1e-4).

#define DIST_SCALE 25.0f
#define T_THRESH   1e-4f
#define FULLMASK   0xffffffffu
#define SEGW       16
#define SPEC       13   // lanes with speculative rgb loads (52 samples)

__device__ __forceinline__ float clip01(float v) {
    return fminf(fmaxf(v, 0.0f), 1.0f);
}

struct Factors { float w0, w1, w2, w3, p; };

__device__ __forceinline__ Factors factors(const float4& sg, const float4& dt) {
    const float f0 = __expf(-DIST_SCALE * sg.x * dt.x);
    const float f1 = __expf(-DIST_SCALE * sg.y * dt.y);
    const float f2 = __expf(-DIST_SCALE * sg.z * dt.z);
    const float f3 = __expf(-DIST_SCALE * sg.w * dt.w);
    const float g0 = f0 + 1e-10f;
    const float g1 = f1 + 1e-10f;
    const float g2 = f2 + 1e-10f;
    const float g3 = f3 + 1e-10f;
    Factors r;
    r.w0 = (1.0f - f0);
    float t = g0;
    r.w1 = (1.0f - f1) * t;  t *= g1;
    r.w2 = (1.0f - f2) * t;  t *= g2;
    r.w3 = (1.0f - f3) * t;
    r.p  = t * g3;
    return r;
}

// Width-16 segment scan: exclusive prefix product + segment total.
__device__ __forceinline__ void seg_scan(float p, int slane, float& excl, float& total) {
    float incl = p;
    #pragma unroll
    for (int off = 1; off < SEGW; off <<= 1) {
        const float v = __shfl_up_sync(FULLMASK, incl, off, SEGW);
        if (slane >= off) incl *= v;
    }
    excl = __shfl_up_sync(FULLMASK, incl, 1, SEGW);
    if (slane == 0) excl = 1.0f;
    total = __shfl_sync(FULLMASK, incl, SEGW - 1, SEGW);
}

__global__ __launch_bounds__(256, 6)
void nerf_composite_kernel(const float4* __restrict__ sigma4,
                           const float4* __restrict__ dists4,
                           const float4* __restrict__ rgb4,
                           const float*  __restrict__ bg,
                           float*        __restrict__ out,
                           int B)
{
    const int warp  = (int)((blockIdx.x * (unsigned)blockDim.x + threadIdx.x) >> 5);
    const int lane  = threadIdx.x & 31;
    const int slane = lane & (SEGW - 1);
    const int ray   = warp * 2 + (lane >> 4);
    if (ray >= B) return;

    float accW = 0.0f, accR = 0.0f, accG = 0.0f, accB = 0.0f;

    // ---- Round 0 (peeled): speculative, single latency exposure ----
    const int  idx0  = ray * 128 + slane;
    const int  ridx0 = ray * 384 + slane * 3;
    const bool spec  = (slane < SPEC);

    const float4 sg = sigma4[idx0];
    const float4 dt = dists4[idx0];
    float4 q0 = make_float4(0.f, 0.f, 0.f, 0.f);
    float4 q1 = q0, q2 = q0;
    if (spec) {                      // independent of sg/dt -> batched in flight
        q0 = rgb4[ridx0 + 0];
        q1 = rgb4[ridx0 + 1];
        q2 = rgb4[ridx0 + 2];
    }

    Factors fc = factors(sg, dt);
    float excl, total;
    seg_scan(fc.p, slane, excl, total);
    const float Tl0 = excl;          // T_run == 1 in round 0

    if (!spec && (Tl0 >= T_THRESH)) {        // rare tail lanes (~0.9% of rays)
        q0 = rgb4[ridx0 + 0];
        q1 = rgb4[ridx0 + 1];
        q2 = rgb4[ridx0 + 2];
    }
    if (spec || (Tl0 >= T_THRESH)) {
        const float w0 = fc.w0 * Tl0, w1 = fc.w1 * Tl0,
                    w2 = fc.w2 * Tl0, w3 = fc.w3 * Tl0;
        accR += w0 * clip01(q0.x) + w1 * clip01(q0.w)
              + w2 * clip01(q1.z) + w3 * clip01(q2.y);
        accG += w0 * clip01(q0.y) + w1 * clip01(q1.x)
              + w2 * clip01(q1.w) + w3 * clip01(q2.z);
        accB += w0 * clip01(q0.z) + w1 * clip01(q1.y)
              + w2 * clip01(q2.x) + w3 * clip01(q2.w);
        accW += w0 + w1 + w2 + w3;
    }

    float T_run = total;

    // ---- Rounds 1..7: conditional path, entered by ~0.01% of rays ----
    if (!__all_sync(FULLMASK, T_run < T_THRESH)) {
        #pragma unroll 1
        for (int k = 1; k < 8; ++k) {
            const int idx = ray * 128 + k * 16 + slane;
            const float4 sgk = sigma4[idx];
            const float4 dtk = dists4[idx];

            Factors fck = factors(sgk, dtk);
            float exclk, totalk;
            seg_scan(fck.p, slane, exclk, totalk);
            const float Tl = T_run * exclk;

            if (Tl >= T_THRESH) {
                const int ridx = ray * 384 + k * 48 + slane * 3;
                const float4 a0 = rgb4[ridx + 0];
                const float4 a1 = rgb4[ridx + 1];
                const float4 a2 = rgb4[ridx + 2];
                const float w0 = fck.w0 * Tl, w1 = fck.w1 * Tl,
                            w2 = fck.w2 * Tl, w3 = fck.w3 * Tl;
                accR += w0 * clip01(a0.x) + w1 * clip01(a0.w)
                      + w2 * clip01(a1.z) + w3 * clip01(a2.y);
                accG += w0 * clip01(a0.y) + w1 * clip01(a1.x)
                      + w2 * clip01(a1.w) + w3 * clip01(a2.z);
                accB += w0 * clip01(a0.z) + w1 * clip01(a1.y)
                      + w2 * clip01(a2.x) + w3 * clip01(a2.w);
                accW += w0 + w1 + w2 + w3;
            }

            T_run *= totalk;
            if (__all_sync(FULLMASK, T_run < T_THRESH)) break;
        }
    }

    // ---- Segment reduction + output ----
    #pragma unroll
    for (int off = SEGW / 2; off >= 1; off >>= 1) {
        accW += __shfl_down_sync(FULLMASK, accW, off, SEGW);
        accR += __shfl_down_sync(FULLMASK, accR, off, SEGW);
        accG += __shfl_down_sync(FULLMASK, accG, off, SEGW);
        accB += __shfl_down_sync(FULLMASK, accB, off, SEGW);
    }

    if (slane == 0) {
        const float rem = 1.0f - accW;
        out[ray * 3 + 0] = accR + rem * __ldg(&bg[0]);
        out[ray * 3 + 1] = accG + rem * __ldg(&bg[1]);
        out[ray * 3 + 2] = accB + rem * __ldg(&bg[2]);
    }
}

extern "C" void kernel_launch(void* const* d_in, const int* in_sizes, int n_in,
                              void* d_out, int out_size)
{
    const float4* sigma4 = (const float4*)d_in[0];
    const float4* dists4 = (const float4*)d_in[1];
    const float4* rgb4   = (const float4*)d_in[2];
    const float*  bg     = (const float*) d_in[3];
    float*        out    = (float*)d_out;

    const int B = in_sizes[0] / 512;           // 65536 rays
    const int threads = 256;                    // 8 warps/block -> 16 rays/block
    const int blocks  = (B + 15) / 16;

    nerf_composite_kernel<<<blocks, threads>>>(sigma4, dists4, rgb4, bg, out, B);
}

// round 12
// speedup vs baseline: 1.0268x; 1.0268x over previous
#include <cuda_runtime.h>

// NeRF volume rendering compositing — round 12: persistent grid.
// Structure inside the ray loop = round-8 winner (two rays/warp, 16-lane
// segments, 64-sample rounds, 4 samples/lane, float4 default-cached loads,
// scan-predicated rgb, tau=1e-4). Change: launch exactly one wave of
// blocks (148 SMs x 8 blocks) and loop each warp over ray-pairs with a
// grid-wide stride — removes ~2.4 wave transitions (~1.2us each) and the
// per-wave straggler tail; early-terminating warps immediately take the
// next ray pair.
// Inputs (metadata order):
//   d_in[0]: sigma  [B, S]    float32   (B=65536, S=512)
//   d_in[1]: dists  [B, S]    float32
//   d_in[2]: rgb    [B, S, 3] float32
//   d_in[3]: bg_col [3]       float32
// Output: rgb_map [B, 3] float32
//
//   x = sigma*dists*25; alpha = 1-exp(-x); T = excl cumprod(exp(-x)+1e-10)
//   w = alpha*T; out_c = sum w*clip(rgb,0,1) + (1-sum w)*bg_c
// Early termination at T < 1e-4: skipped mass telescopes to < 1e-4 abs;
// measured coefficient ~0.64*tau -> rel_err ~6.4e-5 (R8-identical math).

#define DIST_SCALE 25.0f
#define T_THRESH   1e-4f
#define FULLMASK   0xffffffffu
#define SEGW       16
#define NSM        148
#define BLKS_PER_SM 8

__device__ __forceinline__ float clip01(float v) {
    return fminf(fmaxf(v, 0.0f), 1.0f);
}

__global__ __launch_bounds__(256, 8)
void nerf_composite_kernel(const float4* __restrict__ sigma4,
                           const float4* __restrict__ dists4,
                           const float4* __restrict__ rgb4,
                           const float*  __restrict__ bg,
                           float*        __restrict__ out,
                           int B)
{
    const int lane   = threadIdx.x & 31;
    const int slane  = lane & (SEGW - 1);         // lane within 16-lane segment
    const int gwarp  = (int)((blockIdx.x * (unsigned)blockDim.x + threadIdx.x) >> 5);
    const int nwarps = (int)((gridDim.x * (unsigned)blockDim.x) >> 5);

    const int ray0      = gwarp * 2 + (lane >> 4);  // this half-warp's first ray
    const int rayStride = nwarps * 2;               // interleaved striding

    const float bg0 = __ldg(&bg[0]);
    const float bg1 = __ldg(&bg[1]);
    const float bg2 = __ldg(&bg[2]);

    for (int ray = ray0; ray < B; ray += rayStride) {
        float T_run = 1.0f;          // uniform within the segment
        float accW = 0.0f, accR = 0.0f, accG = 0.0f, accB = 0.0f;

        // S = 512 samples = 8 rounds of 64 (4 samples/lane, float4 loads).
        #pragma unroll 1
        for (int k = 0; k < 8; ++k) {
            const int idx = ray * 128 + k * 16 + slane;   // float4 index
            const float4 sg = sigma4[idx];
            const float4 dt = dists4[idx];

            // Transmittance factors f = exp(-sigma*dist*25)
            const float f0 = __expf(-DIST_SCALE * sg.x * dt.x);
            const float f1 = __expf(-DIST_SCALE * sg.y * dt.y);
            const float f2 = __expf(-DIST_SCALE * sg.z * dt.z);
            const float f3 = __expf(-DIST_SCALE * sg.w * dt.w);

            const float g0 = f0 + 1e-10f;
            const float g1 = f1 + 1e-10f;
            const float g2 = f2 + 1e-10f;
            const float g3 = f3 + 1e-10f;

            float w0 = (1.0f - f0);
            float t  = g0;
            float w1 = (1.0f - f1) * t;  t *= g1;
            float w2 = (1.0f - f2) * t;  t *= g2;
            float w3 = (1.0f - f3) * t;
            const float p = t * g3;      // product of this lane's 4 factors

            // Segment (width-16) inclusive prefix product
            float incl = p;
            #pragma unroll
            for (int off = 1; off < SEGW; off <<= 1) {
                const float v = __shfl_up_sync(FULLMASK, incl, off, SEGW);
                if (slane >= off) incl *= v;
            }
            float excl = __shfl_up_sync(FULLMASK, incl, 1, SEGW);
            if (slane == 0) excl = 1.0f;
            const float total = __shfl_sync(FULLMASK, incl, SEGW - 1, SEGW);

            const float Tl = T_run * excl;   // T at this lane's first sample

            // Lanes with negligible remaining transmittance skip rgb traffic.
            if (Tl >= T_THRESH) {
                const int ridx = ray * 384 + k * 48 + slane * 3;
                const float4 q0 = rgb4[ridx + 0];
                const float4 q1 = rgb4[ridx + 1];
                const float4 q2 = rgb4[ridx + 2];

                w0 *= Tl; w1 *= Tl; w2 *= Tl; w3 *= Tl;

                accR += w0 * clip01(q0.x) + w1 * clip01(q0.w)
                      + w2 * clip01(q1.z) + w3 * clip01(q2.y);
                accG += w0 * clip01(q0.y) + w1 * clip01(q1.x)
                      + w2 * clip01(q1.w) + w3 * clip01(q2.z);
                accB += w0 * clip01(q0.z) + w1 * clip01(q1.y)
                      + w2 * clip01(q2.x) + w3 * clip01(q2.w);
                accW += w0 + w1 + w2 + w3;
            }

            T_run *= total;                          // segment-uniform
            const bool done = (T_run < T_THRESH);
            if (__all_sync(FULLMASK, done)) break;   // warp-uniform early exit
        }

        // Segment (width-16) reduction
        #pragma unroll
        for (int off = SEGW / 2; off >= 1; off >>= 1) {
            accW += __shfl_down_sync(FULLMASK, accW, off, SEGW);
            accR += __shfl_down_sync(FULLMASK, accR, off, SEGW);
            accG += __shfl_down_sync(FULLMASK, accG, off, SEGW);
            accB += __shfl_down_sync(FULLMASK, accB, off, SEGW);
        }

        if (slane == 0) {
            const float rem = 1.0f - accW;
            out[ray * 3 + 0] = accR + rem * bg0;
            out[ray * 3 + 1] = accG + rem * bg1;
            out[ray * 3 + 2] = accB + rem * bg2;
        }
    }
}

extern "C" void kernel_launch(void* const* d_in, const int* in_sizes, int n_in,
                              void* d_out, int out_size)
{
    const float4* sigma4 = (const float4*)d_in[0];
    const float4* dists4 = (const float4*)d_in[1];
    const float4* rgb4   = (const float4*)d_in[2];
    const float*  bg     = (const float*) d_in[3];
    float*        out    = (float*)d_out;

    const int B = in_sizes[0] / 512;           // 65536 rays
    const int threads = 256;                    // 8 warps/block
    const int blocks  = NSM * BLKS_PER_SM;      // one persistent wave (1184)

    nerf_composite_kernel<<<blocks, threads>>>(sigma4, dists4, rgb4, bg, out, B);
}

// round 13
// speedup vs baseline: 1.1679x; 1.1374x over previous
#include <cuda_runtime.h>

// NeRF volume rendering compositing — round 13: R8 platform, finer blocks.
// Math/cache/tau identical to round-8 best (12.64us): two rays per warp
// (16-lane segments), 64-sample rounds, 4 samples/lane, float4 default-
// cached loads (working set ~65MB stays L2-resident across graph replays),
// scan-predicated rgb, tau=1e-4. Single change: 128-thread blocks (8192
// blocks, 16/SM, same 2048 threads/SM, regs 32) — no __syncthreads exists,
// so block size only affects dynamic scheduling granularity / tail balance.
// Also serves as the R8 reproducibility re-bench (rel_err must be bit-
// identical: 6.380106e-5).
// Inputs (metadata order):
//   d_in[0]: sigma  [B, S]    float32   (B=65536, S=512)
//   d_in[1]: dists  [B, S]    float32
//   d_in[2]: rgb    [B, S, 3] float32
//   d_in[3]: bg_col [3]       float32
// Output: rgb_map [B, 3] float32
//
//   x = sigma*dists*25; alpha = 1-exp(-x); T = excl cumprod(exp(-x)+1e-10)
//   w = alpha*T; out_c = sum w*clip(rgb,0,1) + (1-sum w)*bg_c
// Early termination at T < 1e-4: skipped mass telescopes to < 1e-4 abs;
// measured coefficient ~0.64*tau -> rel_err ~6.4e-5 vs the 1e-3 gate.

#define DIST_SCALE 25.0f
#define T_THRESH   1e-4f
#define FULLMASK   0xffffffffu
#define SEGW       16

__device__ __forceinline__ float clip01(float v) {
    return fminf(fmaxf(v, 0.0f), 1.0f);
}

__global__ __launch_bounds__(128, 16)
void nerf_composite_kernel(const float4* __restrict__ sigma4,
                           const float4* __restrict__ dists4,
                           const float4* __restrict__ rgb4,
                           const float*  __restrict__ bg,
                           float*        __restrict__ out,
                           int B)
{
    const int warp  = (int)((blockIdx.x * (unsigned)blockDim.x + threadIdx.x) >> 5);
    const int lane  = threadIdx.x & 31;
    const int slane = lane & (SEGW - 1);        // lane within 16-lane segment
    const int ray   = warp * 2 + (lane >> 4);   // one ray per half-warp
    if (ray >= B) return;

    float T_run = 1.0f;          // uniform within the segment
    float accW = 0.0f, accR = 0.0f, accG = 0.0f, accB = 0.0f;

    // S = 512 samples = 8 rounds of 64 (4 samples/lane, float4 loads).
    #pragma unroll 1
    for (int k = 0; k < 8; ++k) {
        const int idx = ray * 128 + k * 16 + slane;   // float4 index into sigma/dists
        const float4 sg = sigma4[idx];
        const float4 dt = dists4[idx];

        // Transmittance factors f = exp(-sigma*dist*25)
        const float f0 = __expf(-DIST_SCALE * sg.x * dt.x);
        const float f1 = __expf(-DIST_SCALE * sg.y * dt.y);
        const float f2 = __expf(-DIST_SCALE * sg.z * dt.z);
        const float f3 = __expf(-DIST_SCALE * sg.w * dt.w);

        const float g0 = f0 + 1e-10f;
        const float g1 = f1 + 1e-10f;
        const float g2 = f2 + 1e-10f;
        const float g3 = f3 + 1e-10f;

        float w0 = (1.0f - f0);
        float t  = g0;
        float w1 = (1.0f - f1) * t;  t *= g1;
        float w2 = (1.0f - f2) * t;  t *= g2;
        float w3 = (1.0f - f3) * t;
        const float p = t * g3;      // product of this lane's 4 factors

        // Segment (width-16) inclusive prefix product of p
        float incl = p;
        #pragma unroll
        for (int off = 1; off < SEGW; off <<= 1) {
            const float v = __shfl_up_sync(FULLMASK, incl, off, SEGW);
            if (slane >= off) incl *= v;
        }
        float excl = __shfl_up_sync(FULLMASK, incl, 1, SEGW);
        if (slane == 0) excl = 1.0f;
        const float total = __shfl_sync(FULLMASK, incl, SEGW - 1, SEGW);

        const float Tl = T_run * excl;   // transmittance at this lane's first sample

        // Lanes with negligible remaining transmittance skip rgb traffic.
        if (Tl >= T_THRESH) {
            const int ridx = ray * 384 + k * 48 + slane * 3;   // float4 index into rgb
            const float4 q0 = rgb4[ridx + 0];
            const float4 q1 = rgb4[ridx + 1];
            const float4 q2 = rgb4[ridx + 2];

            w0 *= Tl; w1 *= Tl; w2 *= Tl; w3 *= Tl;

            accR += w0 * clip01(q0.x) + w1 * clip01(q0.w)
                  + w2 * clip01(q1.z) + w3 * clip01(q2.y);
            accG += w0 * clip01(q0.y) + w1 * clip01(q1.x)
                  + w2 * clip01(q1.w) + w3 * clip01(q2.z);
            accB += w0 * clip01(q0.z) + w1 * clip01(q1.y)
                  + w2 * clip01(q2.x) + w3 * clip01(q2.w);
            accW += w0 + w1 + w2 + w3;
        }

        T_run *= total;                          // stays segment-uniform
        const bool done = (T_run < T_THRESH);
        if (__all_sync(FULLMASK, done)) break;   // warp-uniform early exit
        // A finished segment keeps looping but Tl < thresh suppresses all
        // its rgb traffic and accumulation — correctness unaffected.
    }

    // Segment (width-16) reduction
    #pragma unroll
    for (int off = SEGW / 2; off >= 1; off >>= 1) {
        accW += __shfl_down_sync(FULLMASK, accW, off, SEGW);
        accR += __shfl_down_sync(FULLMASK, accR, off, SEGW);
        accG += __shfl_down_sync(FULLMASK, accG, off, SEGW);
        accB += __shfl_down_sync(FULLMASK, accB, off, SEGW);
    }

    if (slane == 0) {
        const float rem = 1.0f - accW;
        out[ray * 3 + 0] = accR + rem * __ldg(&bg[0]);
        out[ray * 3 + 1] = accG + rem * __ldg(&bg[1]);
        out[ray * 3 + 2] = accB + rem * __ldg(&bg[2]);
    }
}

extern "C" void kernel_launch(void* const* d_in, const int* in_sizes, int n_in,
                              void* d_out, int out_size)
{
    const float4* sigma4 = (const float4*)d_in[0];
    const float4* dists4 = (const float4*)d_in[1];
    const float4* rgb4   = (const float4*)d_in[2];
    const float*  bg     = (const float*) d_in[3];
    float*        out    = (float*)d_out;

    const int B = in_sizes[0] / 512;           // 65536 rays
    const int threads = 128;                    // 4 warps/block -> 8 rays/block
    const int blocks  = (B + 7) / 8;            // 8192 blocks

    nerf_composite_kernel<<<blocks, threads>>>(sigma4, dists4, rgb4, bg, out, B);
}